// round 3
// baseline (speedup 1.0000x reference)
#include <cuda_runtime.h>
#include <cstdint>

#define NN 50000
#define EE 600000
#define HIDD 128
#define NH 8
#define DDIM 16

// ---------------- scratch (device globals; no allocation allowed) ----------------
__device__ float g_Qh[(size_t)NN * HIDD];
__device__ float g_Kh[(size_t)NN * HIDD];
__device__ float g_Vh[(size_t)NN * HIDD];
__device__ float g_ce[(size_t)EE * HIDD];  // conn_e / e_attn
__device__ float g_ssum[(size_t)NN * NH];
__device__ float g_agg[(size_t)NN * HIDD];
__device__ float g_row[(size_t)NN * HIDD];
__device__ float g_hpre[(size_t)NN * HIDD];
__device__ float g_h1[(size_t)NN * HIDD];
__device__ float g_mlp[(size_t)NN * 256];

__device__ __forceinline__ float to_tf32(float x) {
    float r;
    asm("cvt.rna.tf32.f32 %0, %1;" : "=f"(r) : "f"(x));
    return r;
}

__device__ __forceinline__ void mma8(float* c, const uint32_t* a, const uint32_t* b) {
    asm volatile(
        "mma.sync.aligned.m16n8k8.row.col.f32.tf32.tf32.f32 "
        "{%0,%1,%2,%3},{%4,%5,%6,%7},{%8,%9},{%0,%1,%2,%3};"
        : "+f"(c[0]), "+f"(c[1]), "+f"(c[2]), "+f"(c[3])
        : "r"(a[0]), "r"(a[1]), "r"(a[2]), "r"(a[3]), "r"(b[0]), "r"(b[1]));
}

// ---------------- TF32 tensor-core GEMM (unchanged from R2) ----------------
#define SMS 136
template <int KD, int EPI>
__global__ void __launch_bounds__(256) tgemm(
    const float* __restrict__ A, const float* __restrict__ W, int ldw,
    const float* __restrict__ bias, const float* __restrict__ resid,
    const float* __restrict__ lng, const float* __restrict__ lnb,
    float* __restrict__ C, int ldc, int M)
{
    __shared__ float As[16][SMS];
    __shared__ float Ws[16][SMS];

    const int t = threadIdx.x;
    const int lane = t & 31;
    const int wid = t >> 5;
    const int m0b = blockIdx.x * 128;
    const int n0 = blockIdx.y * 128;
    const int wm0 = wid * 16;
    const int gr = lane >> 2;
    const int kq = lane & 3;

    float acc[16][4];
#pragma unroll
    for (int i = 0; i < 16; i++) { acc[i][0] = acc[i][1] = acc[i][2] = acc[i][3] = 0.f; }

    const int arow = t >> 2;
    const int acol = (t & 3) * 4;
    const int wrow = t >> 5;
    const int wcol = (t & 31) * 4;

    for (int kt = 0; kt < KD; kt += 16) {
#pragma unroll
        for (int p = 0; p < 2; p++) {
            int r = arow + p * 64;
            float4 v = make_float4(0.f, 0.f, 0.f, 0.f);
            if (m0b + r < M) v = *(const float4*)&A[(size_t)(m0b + r) * KD + kt + acol];
            As[acol + 0][r] = to_tf32(v.x); As[acol + 1][r] = to_tf32(v.y);
            As[acol + 2][r] = to_tf32(v.z); As[acol + 3][r] = to_tf32(v.w);
        }
#pragma unroll
        for (int p = 0; p < 2; p++) {
            int kr = wrow + p * 8;
            float4 v = *(const float4*)&W[(size_t)(kt + kr) * ldw + n0 + wcol];
            Ws[kr][wcol + 0] = to_tf32(v.x); Ws[kr][wcol + 1] = to_tf32(v.y);
            Ws[kr][wcol + 2] = to_tf32(v.z); Ws[kr][wcol + 3] = to_tf32(v.w);
        }
        __syncthreads();
#pragma unroll
        for (int ks = 0; ks < 16; ks += 8) {
            uint32_t a[4];
            a[0] = __float_as_uint(As[ks + kq][wm0 + gr]);
            a[1] = __float_as_uint(As[ks + kq][wm0 + 8 + gr]);
            a[2] = __float_as_uint(As[ks + 4 + kq][wm0 + gr]);
            a[3] = __float_as_uint(As[ks + 4 + kq][wm0 + 8 + gr]);
#pragma unroll
            for (int nf = 0; nf < 16; nf++) {
                uint32_t b[2];
                b[0] = __float_as_uint(Ws[ks + kq][nf * 8 + gr]);
                b[1] = __float_as_uint(Ws[ks + 4 + kq][nf * 8 + gr]);
                mma8(acc[nf], a, b);
            }
        }
        __syncthreads();
    }

    if (EPI == 0 || EPI == 1) {
#pragma unroll
        for (int half = 0; half < 2; half++) {
            int r = m0b + wm0 + gr + half * 8;
            if (r >= M) continue;
#pragma unroll
            for (int nf = 0; nf < 16; nf++) {
                int c = n0 + nf * 8 + 2 * kq;
                float v0 = acc[nf][half * 2 + 0];
                float v1 = acc[nf][half * 2 + 1];
                if (bias) { v0 += bias[c]; v1 += bias[c + 1]; }
                if (EPI == 1) { v0 = fmaxf(v0, 0.f); v1 = fmaxf(v1, 0.f); }
                *(float2*)&C[(size_t)r * ldc + c] = make_float2(v0, v1);
            }
        }
    } else {
        float v[32];
#pragma unroll
        for (int half = 0; half < 2; half++) {
            int r = m0b + wm0 + gr + half * 8;
            bool ok = (r < M);
            float s = 0.f, s2 = 0.f;
#pragma unroll
            for (int nf = 0; nf < 16; nf++) {
                int c = nf * 8 + 2 * kq;
                float x0 = acc[nf][half * 2 + 0] + bias[c];
                float x1 = acc[nf][half * 2 + 1] + bias[c + 1];
                if (ok) {
                    float2 rr = *(const float2*)&resid[(size_t)r * 128 + c];
                    x0 += rr.x; x1 += rr.y;
                }
                v[2 * nf] = x0; v[2 * nf + 1] = x1;
                s += x0 + x1;
                s2 += x0 * x0 + x1 * x1;
            }
#pragma unroll
            for (int off = 1; off < 4; off <<= 1) {
                s += __shfl_xor_sync(0xffffffffu, s, off);
                s2 += __shfl_xor_sync(0xffffffffu, s2, off);
            }
            float mean = s * (1.f / 128.f);
            float var = s2 * (1.f / 128.f) - mean * mean;
            float rstd = rsqrtf(var + 1e-5f);
            if (ok) {
#pragma unroll
                for (int nf = 0; nf < 16; nf++) {
                    int c = nf * 8 + 2 * kq;
                    float o0 = (v[2 * nf] - mean) * rstd * lng[c] + lnb[c];
                    float o1 = (v[2 * nf + 1] - mean) * rstd * lng[c + 1] + lnb[c + 1];
                    *(float2*)&C[(size_t)r * 128 + c] = make_float2(o0, o1);
                }
            }
        }
    }
}

// ---------------- fused Eh-GEMM + edge pass ----------------
// Block = 64 edges. A-tile (conn 64x128, tf32) resident in smem for all K.
// Warp w: mg = w>>1 (16-edge group), nh = w&1 (Ew half / Eb half).
// Smem floats: As[128][72] | Ws[16][264] | ebuf[64][132]
#define AS_STRIDE 72
#define WS_STRIDE 264
#define EB_STRIDE 132
#define FUSED_SMEM ((128 * AS_STRIDE + 16 * WS_STRIDE + 64 * EB_STRIDE) * 4)

__global__ void __launch_bounds__(256) eh_edge_kernel(
    const float* __restrict__ conn, const float* __restrict__ WE,
    const int* __restrict__ ei, const float* __restrict__ Aw)
{
    extern __shared__ float sm[];
    float* As = sm;                            // [128][AS_STRIDE], As[k][m]
    float* Ws = As + 128 * AS_STRIDE;          // [16][WS_STRIDE]
    float* ebuf = Ws + 16 * WS_STRIDE;         // [64][EB_STRIDE]

    const int t = threadIdx.x;
    const int lane = t & 31;
    const int w = t >> 5;
    const int mg = w >> 1;
    const int nh = w & 1;
    const int gr = lane >> 2;
    const int kq = lane & 3;
    const int e0 = blockIdx.x * 64;            // EE % 64 == 0

    // ---- load A tile (conn rows e0..e0+63) transposed into As[k][m] ----
    {
        int r = t >> 2;
        int cb = (t & 3) * 32;
#pragma unroll
        for (int j = 0; j < 8; j++) {
            float4 v = *(const float4*)&conn[(size_t)(e0 + r) * 128 + cb + j * 4];
            As[(cb + j * 4 + 0) * AS_STRIDE + r] = to_tf32(v.x);
            As[(cb + j * 4 + 1) * AS_STRIDE + r] = to_tf32(v.y);
            As[(cb + j * 4 + 2) * AS_STRIDE + r] = to_tf32(v.z);
            As[(cb + j * 4 + 3) * AS_STRIDE + r] = to_tf32(v.w);
        }
    }
    __syncthreads();

    // ---- GEMM: acc = conn @ WE[:, nh*128 : nh*128+128] for 16 edges ----
    float acc[16][4];
#pragma unroll
    for (int i = 0; i < 16; i++) { acc[i][0] = acc[i][1] = acc[i][2] = acc[i][3] = 0.f; }

    const int wrow = t >> 4;                   // 0..15
    const int wcol = (t & 15) * 16;            // 0..240

    for (int kt = 0; kt < 8; kt++) {
        // load W slice rows kt*16..+15, all 256 cols
#pragma unroll
        for (int j = 0; j < 4; j++) {
            float4 v = *(const float4*)&WE[(size_t)(kt * 16 + wrow) * 256 + wcol + j * 4];
            Ws[wrow * WS_STRIDE + wcol + j * 4 + 0] = to_tf32(v.x);
            Ws[wrow * WS_STRIDE + wcol + j * 4 + 1] = to_tf32(v.y);
            Ws[wrow * WS_STRIDE + wcol + j * 4 + 2] = to_tf32(v.z);
            Ws[wrow * WS_STRIDE + wcol + j * 4 + 3] = to_tf32(v.w);
        }
        __syncthreads();
#pragma unroll
        for (int ks = 0; ks < 16; ks += 8) {
            int kbase = kt * 16 + ks;
            uint32_t a[4];
            a[0] = __float_as_uint(As[(kbase + kq) * AS_STRIDE + mg * 16 + gr]);
            a[1] = __float_as_uint(As[(kbase + kq) * AS_STRIDE + mg * 16 + 8 + gr]);
            a[2] = __float_as_uint(As[(kbase + 4 + kq) * AS_STRIDE + mg * 16 + gr]);
            a[3] = __float_as_uint(As[(kbase + 4 + kq) * AS_STRIDE + mg * 16 + 8 + gr]);
#pragma unroll
            for (int nf = 0; nf < 16; nf++) {
                uint32_t b[2];
                b[0] = __float_as_uint(Ws[(ks + kq) * WS_STRIDE + nh * 128 + nf * 8 + gr]);
                b[1] = __float_as_uint(Ws[(ks + 4 + kq) * WS_STRIDE + nh * 128 + nf * 8 + gr]);
                mma8(acc[nf], a, b);
            }
        }
        __syncthreads();
    }

    // ---- Eb warps stash their half into ebuf ----
    if (nh == 1) {
#pragma unroll
        for (int half = 0; half < 2; half++) {
            int r = mg * 16 + gr + half * 8;
#pragma unroll
            for (int nf = 0; nf < 16; nf++) {
                int c = nf * 8 + 2 * kq;
                *(float2*)&ebuf[r * EB_STRIDE + c] =
                    make_float2(acc[nf][half * 2 + 0], acc[nf][half * 2 + 1]);
            }
        }
    }
    __syncthreads();

    // ---- Ew warps: ce = relu(signed_sqrt((Qh[dst]+Kh[src]) * Ew) + Eb) ----
    if (nh == 0) {
#pragma unroll
        for (int half = 0; half < 2; half++) {
            int r = mg * 16 + gr + half * 8;
            int e = e0 + r;
            int dst = ei[e];
            int src = ei[EE + e];
            const float* qrow = &g_Qh[(size_t)dst * HIDD];
            const float* krow = &g_Kh[(size_t)src * HIDD];
#pragma unroll
            for (int nf = 0; nf < 16; nf++) {
                int c = nf * 8 + 2 * kq;
                float2 q = *(const float2*)&qrow[c];
                float2 k = *(const float2*)&krow[c];
                float2 eb = *(const float2*)&ebuf[r * EB_STRIDE + c];
                float m0 = q.x + k.x, m1 = q.y + k.y;
                float cc0 = m0 * acc[nf][half * 2 + 0];
                float cc1 = m1 * acc[nf][half * 2 + 1];
                float ss0 = sqrtf(fabsf(cc0)); ss0 = (cc0 >= 0.f) ? ss0 : -ss0;
                float ss1 = sqrtf(fabsf(cc1)); ss1 = (cc1 >= 0.f) ? ss1 : -ss1;
                float ce0 = fmaxf(ss0 + eb.x, 0.f);
                float ce1 = fmaxf(ss1 + eb.y, 0.f);
                *(float2*)&ebuf[r * EB_STRIDE + c] = make_float2(ce0, ce1);
                *(float2*)&g_ce[(size_t)e * HIDD + c] = make_float2(ce0, ce1);
            }
        }
    }
    __syncthreads();

    // ---- per-edge softmax + segment atomics (8 edges per warp) ----
    {
        int c0 = lane * 4;
        int h = lane >> 2;
        int dbase = (lane & 3) * 4;
#pragma unroll
        for (int i = 0; i < 8; i++) {
            int r = w * 8 + i;
            int e = e0 + r;
            int dst = ei[e];
            int src = ei[EE + e];
            float4 ce4 = *(const float4*)&ebuf[r * EB_STRIDE + c0];
            const float* cf = (const float*)&ce4;
            float part = 0.f;
#pragma unroll
            for (int j = 0; j < 4; j++)
                part += cf[j] * Aw[(dbase + j) * NH + h];
            part += __shfl_xor_sync(0xffffffffu, part, 1);
            part += __shfl_xor_sync(0xffffffffu, part, 2);
            float s = fminf(fmaxf(part, -5.f), 5.f);
            float p = __expf(s);

            if ((lane & 3) == 0) atomicAdd(&g_ssum[(size_t)dst * NH + h], p);
            float4 v4 = *(const float4*)&g_Vh[(size_t)src * HIDD + c0];
            float4 av = make_float4(v4.x * p, v4.y * p, v4.z * p, v4.w * p);
            float4 rv = make_float4(ce4.x * p, ce4.y * p, ce4.z * p, ce4.w * p);
            atomicAdd((float4*)&g_agg[(size_t)dst * HIDD + c0], av);
            atomicAdd((float4*)&g_row[(size_t)dst * HIDD + c0], rv);
        }
    }
}

// ---------------- node pass (unchanged) ----------------
__global__ void __launch_bounds__(256) node_kernel(const float* __restrict__ Bw,
                                                   const float* __restrict__ deg_coef,
                                                   const float* __restrict__ log_deg)
{
    __shared__ float rbuf[8][HIDD];
    int n = (int)((blockIdx.x * (size_t)blockDim.x + threadIdx.x) >> 5);
    int wl = (threadIdx.x >> 5) & 7;
    int l = threadIdx.x & 31;
    if (n >= NN) return;
    int h = l >> 2;
    int c0 = l * 4;

    float rs = 1.f / (g_ssum[(size_t)n * NH + h] + 1e-16f);
    float4 a = *(const float4*)&g_agg[(size_t)n * HIDD + c0];
    float4 r = *(const float4*)&g_row[(size_t)n * HIDD + c0];
    a.x *= rs; a.y *= rs; a.z *= rs; a.w *= rs;
    r.x *= rs; r.y *= rs; r.z *= rs; r.w *= rs;
    *(float4*)&rbuf[wl][c0] = r;
    __syncwarp();

    float4 q = *(const float4*)&g_Qh[(size_t)n * HIDD + c0];
    const float* af = (const float*)&a;
    const float* qf = (const float*)&q;
    float ld = log_deg[n];

    float out[4];
#pragma unroll
    for (int i = 0; i < 4; i++) {
        int c = c0 + i;
        float rv = 0.f;
#pragma unroll
        for (int d = 0; d < DDIM; d++)
            rv = fmaf(rbuf[wl][h * DDIM + d], __ldg(&Bw[d * HIDD + c]), rv);
        float ha = qf[i] + af[i] + rv;
        out[i] = ha * (deg_coef[2 * c] + ld * deg_coef[2 * c + 1]);
    }
    *(float4*)&g_hpre[(size_t)n * HIDD + c0] = make_float4(out[0], out[1], out[2], out[3]);
}

// ---------------- launch ----------------
extern "C" void kernel_launch(void* const* d_in, const int* in_sizes, int n_in,
                              void* d_out, int out_size)
{
    const float* x        = (const float*)d_in[0];
    const float* conn     = (const float*)d_in[1];
    const float* log_deg  = (const float*)d_in[2];
    const int*   ei       = (const int*)d_in[3];
    const float* WQ       = (const float*)d_in[4];
    const float* WK       = (const float*)d_in[5];
    const float* WV       = (const float*)d_in[6];
    const float* WE       = (const float*)d_in[7];
    const float* Aw       = (const float*)d_in[8];
    const float* Bw       = (const float*)d_in[9];
    const float* Ho_w     = (const float*)d_in[10];
    const float* Ho_b     = (const float*)d_in[11];
    const float* Eo_w     = (const float*)d_in[12];
    const float* Eo_b     = (const float*)d_in[13];
    const float* deg_coef = (const float*)d_in[14];
    const float* ln1h_g   = (const float*)d_in[15];
    const float* ln1h_b   = (const float*)d_in[16];
    const float* ln1e_g   = (const float*)d_in[17];
    const float* ln1e_b   = (const float*)d_in[18];
    const float* ln2h_g   = (const float*)d_in[19];
    const float* ln2h_b   = (const float*)d_in[20];
    const float* W1       = (const float*)d_in[21];
    const float* b1       = (const float*)d_in[22];
    const float* W2       = (const float*)d_in[23];
    const float* b2       = (const float*)d_in[24];

    float* out_h = (float*)d_out;
    float* out_e = out_h + (size_t)NN * HIDD;

    float *Qh, *Kh, *Vh, *ce, *ssum, *agg, *row, *hpre, *h1, *mlp;
    cudaGetSymbolAddress((void**)&Qh, g_Qh);
    cudaGetSymbolAddress((void**)&Kh, g_Kh);
    cudaGetSymbolAddress((void**)&Vh, g_Vh);
    cudaGetSymbolAddress((void**)&ce, g_ce);
    cudaGetSymbolAddress((void**)&ssum, g_ssum);
    cudaGetSymbolAddress((void**)&agg, g_agg);
    cudaGetSymbolAddress((void**)&row, g_row);
    cudaGetSymbolAddress((void**)&hpre, g_hpre);
    cudaGetSymbolAddress((void**)&h1, g_h1);
    cudaGetSymbolAddress((void**)&mlp, g_mlp);

    static bool attr_done = false;
    cudaFuncSetAttribute(eh_edge_kernel, cudaFuncAttributeMaxDynamicSharedMemorySize, FUSED_SMEM);
    (void)attr_done;

    const int gN = (NN + 127) / 128;   // 391
    const int gE = (EE + 127) / 128;   // 4688

    cudaMemsetAsync(ssum, 0, (size_t)NN * NH * sizeof(float), 0);
    cudaMemsetAsync(agg, 0, (size_t)NN * HIDD * sizeof(float), 0);
    cudaMemsetAsync(row, 0, (size_t)NN * HIDD * sizeof(float), 0);

    // Qh, Kh, Vh
    tgemm<128, 0><<<dim3(gN, 1), 256>>>(x, WQ, 128, nullptr, nullptr, nullptr, nullptr, Qh, 128, NN);
    tgemm<128, 0><<<dim3(gN, 1), 256>>>(x, WK, 128, nullptr, nullptr, nullptr, nullptr, Kh, 128, NN);
    tgemm<128, 0><<<dim3(gN, 1), 256>>>(x, WV, 128, nullptr, nullptr, nullptr, nullptr, Vh, 128, NN);

    // fused Eh gemm + edge pass (EE/64 = 9375 blocks)
    eh_edge_kernel<<<EE / 64, 256, FUSED_SMEM>>>(conn, WE, ei, Aw);

    // node pass -> h_pre
    node_kernel<<<(NN * 32 + 255) / 256, 256>>>(Bw, deg_coef, log_deg);

    // h1 = LN1h(x + hpre @ Ho_w + Ho_b)
    tgemm<128, 2><<<dim3(gN, 1), 256>>>(hpre, Ho_w, 128, Ho_b, x, ln1h_g, ln1h_b, h1, 128, NN);
    // mlp = relu(h1 @ W1 + b1)
    tgemm<128, 1><<<dim3(gN, 2), 256>>>(h1, W1, 256, b1, nullptr, nullptr, nullptr, mlp, 256, NN);
    // out_h = LN2h(h1 + mlp @ W2 + b2)
    tgemm<256, 2><<<dim3(gN, 1), 256>>>(mlp, W2, 128, b2, h1, ln2h_g, ln2h_b, out_h, 128, NN);
    // out_e = LN1e(conn + ce @ Eo_w + Eo_b)
    tgemm<128, 2><<<dim3(gE, 1), 256>>>(ce, Eo_w, 128, Eo_b, conn, ln1e_g, ln1e_b, out_e, 128, EE);
}

// round 5
// speedup vs baseline: 1.3531x; 1.3531x over previous
#include <cuda_runtime.h>
#include <cstdint>

#define NN 50000
#define EE 600000
#define HIDD 128
#define NH 8
#define DDIM 16

// ---------------- scratch (device globals; no allocation allowed) ----------------
__device__ float g_Qh[(size_t)NN * HIDD];
__device__ float g_Kh[(size_t)NN * HIDD];
__device__ float g_Vh[(size_t)NN * HIDD];
__device__ float g_Eh[(size_t)EE * 256];   // [Ew | Eb] per edge
__device__ float g_ce[(size_t)EE * HIDD];  // conn_e / e_attn
__device__ float g_ssum[(size_t)NN * NH];
__device__ float g_agg[(size_t)NN * HIDD];
__device__ float g_row[(size_t)NN * HIDD];
__device__ float g_hpre[(size_t)NN * HIDD];
__device__ float g_h1[(size_t)NN * HIDD];
__device__ float g_mlp[(size_t)NN * 256];

__device__ __forceinline__ float to_tf32(float x) {
    float r;
    asm("cvt.rna.tf32.f32 %0, %1;" : "=f"(r) : "f"(x));
    return r;
}

__device__ __forceinline__ void mma8(float* c, const uint32_t* a, const uint32_t* b) {
    asm volatile(
        "mma.sync.aligned.m16n8k8.row.col.f32.tf32.tf32.f32 "
        "{%0,%1,%2,%3},{%4,%5,%6,%7},{%8,%9},{%0,%1,%2,%3};"
        : "+f"(c[0]), "+f"(c[1]), "+f"(c[2]), "+f"(c[3])
        : "r"(a[0]), "r"(a[1]), "r"(a[2]), "r"(a[3]), "r"(b[0]), "r"(b[1]));
}

// ---------------- TF32 tensor-core GEMM with register double-buffered pipeline ----
// 8 warps, warp tile 16(m) x 128(n): each output row lives in one 4-lane group.
// EPI 0: C = acc (+bias)          EPI 1: C = relu(acc + bias)
// EPI 2: C = LN(resid + acc + bias)*g + b  (grid.y==1, ldc==128)
#define SMS 136
template <int KD, int EPI>
__global__ void __launch_bounds__(256) tgemm(
    const float* __restrict__ A, const float* __restrict__ W, int ldw,
    const float* __restrict__ bias, const float* __restrict__ resid,
    const float* __restrict__ lng, const float* __restrict__ lnb,
    float* __restrict__ C, int ldc, int M)
{
    __shared__ float As[16][SMS];
    __shared__ float Ws[16][SMS];

    const int t = threadIdx.x;
    const int lane = t & 31;
    const int wid = t >> 5;
    const int m0b = blockIdx.x * 128;
    const int n0 = blockIdx.y * 128;
    const int wm0 = wid * 16;
    const int gr = lane >> 2;
    const int kq = lane & 3;

    float acc[16][4];
#pragma unroll
    for (int i = 0; i < 16; i++) { acc[i][0] = acc[i][1] = acc[i][2] = acc[i][3] = 0.f; }

    const int arow = t >> 2;           // 0..63
    const int acol = (t & 3) * 4;
    const int wrow = t >> 5;           // 0..7
    const int wcol = (t & 31) * 4;

    float4 aR[2], wR[2];

    // prologue: load k-chunk 0 into registers
#pragma unroll
    for (int p = 0; p < 2; p++) {
        int row = m0b + arow + p * 64;
        aR[p] = make_float4(0.f, 0.f, 0.f, 0.f);
        if (row < M) aR[p] = *(const float4*)&A[(size_t)row * KD + acol];
        int kr = wrow + p * 8;
        wR[p] = *(const float4*)&W[(size_t)kr * ldw + n0 + wcol];
    }

    for (int kt = 0; kt < KD; kt += 16) {
        __syncthreads();   // previous compute done before smem overwrite
#pragma unroll
        for (int p = 0; p < 2; p++) {
            int r = arow + p * 64;
            As[acol + 0][r] = to_tf32(aR[p].x); As[acol + 1][r] = to_tf32(aR[p].y);
            As[acol + 2][r] = to_tf32(aR[p].z); As[acol + 3][r] = to_tf32(aR[p].w);
            int kr = wrow + p * 8;
            Ws[kr][wcol + 0] = to_tf32(wR[p].x); Ws[kr][wcol + 1] = to_tf32(wR[p].y);
            Ws[kr][wcol + 2] = to_tf32(wR[p].z); Ws[kr][wcol + 3] = to_tf32(wR[p].w);
        }
        // issue next chunk's global loads early (overlap with mma below)
        if (kt + 16 < KD) {
#pragma unroll
            for (int p = 0; p < 2; p++) {
                int row = m0b + arow + p * 64;
                aR[p] = make_float4(0.f, 0.f, 0.f, 0.f);
                if (row < M) aR[p] = *(const float4*)&A[(size_t)row * KD + kt + 16 + acol];
                int kr = wrow + p * 8;
                wR[p] = *(const float4*)&W[(size_t)(kt + 16 + kr) * ldw + n0 + wcol];
            }
        }
        __syncthreads();
#pragma unroll
        for (int ks = 0; ks < 16; ks += 8) {
            uint32_t a[4];
            a[0] = __float_as_uint(As[ks + kq][wm0 + gr]);
            a[1] = __float_as_uint(As[ks + kq][wm0 + 8 + gr]);
            a[2] = __float_as_uint(As[ks + 4 + kq][wm0 + gr]);
            a[3] = __float_as_uint(As[ks + 4 + kq][wm0 + 8 + gr]);
#pragma unroll
            for (int nf = 0; nf < 16; nf++) {
                uint32_t b[2];
                b[0] = __float_as_uint(Ws[ks + kq][nf * 8 + gr]);
                b[1] = __float_as_uint(Ws[ks + 4 + kq][nf * 8 + gr]);
                mma8(acc[nf], a, b);
            }
        }
    }

    if (EPI == 0 || EPI == 1) {
#pragma unroll
        for (int half = 0; half < 2; half++) {
            int r = m0b + wm0 + gr + half * 8;
            if (r >= M) continue;
#pragma unroll
            for (int nf = 0; nf < 16; nf++) {
                int c = n0 + nf * 8 + 2 * kq;
                float v0 = acc[nf][half * 2 + 0];
                float v1 = acc[nf][half * 2 + 1];
                if (bias) { v0 += bias[c]; v1 += bias[c + 1]; }
                if (EPI == 1) { v0 = fmaxf(v0, 0.f); v1 = fmaxf(v1, 0.f); }
                *(float2*)&C[(size_t)r * ldc + c] = make_float2(v0, v1);
            }
        }
    } else {
        // LayerNorm epilogue: a row's 128 cols are held by the 4 lanes of one group.
        float v[32];
#pragma unroll
        for (int half = 0; half < 2; half++) {
            int r = m0b + wm0 + gr + half * 8;
            bool ok = (r < M);
            float s = 0.f, s2 = 0.f;
#pragma unroll
            for (int nf = 0; nf < 16; nf++) {
                int c = nf * 8 + 2 * kq;
                float x0 = acc[nf][half * 2 + 0] + bias[c];
                float x1 = acc[nf][half * 2 + 1] + bias[c + 1];
                if (ok) {
                    float2 rr = *(const float2*)&resid[(size_t)r * 128 + c];
                    x0 += rr.x; x1 += rr.y;
                }
                v[2 * nf] = x0; v[2 * nf + 1] = x1;
                s += x0 + x1;
                s2 += x0 * x0 + x1 * x1;
            }
#pragma unroll
            for (int off = 1; off < 4; off <<= 1) {
                s += __shfl_xor_sync(0xffffffffu, s, off);
                s2 += __shfl_xor_sync(0xffffffffu, s2, off);
            }
            float mean = s * (1.f / 128.f);
            float var = s2 * (1.f / 128.f) - mean * mean;
            float rstd = rsqrtf(var + 1e-5f);
            if (ok) {
#pragma unroll
                for (int nf = 0; nf < 16; nf++) {
                    int c = nf * 8 + 2 * kq;
                    float o0 = (v[2 * nf] - mean) * rstd * lng[c] + lnb[c];
                    float o1 = (v[2 * nf + 1] - mean) * rstd * lng[c + 1] + lnb[c + 1];
                    *(float2*)&C[(size_t)r * 128 + c] = make_float2(o0, o1);
                }
            }
        }
    }
}

// ---------------- edge pass: conn_e, scores, segment accumulation ----------------
// one warp per edge. Softmax max-shift dropped (scores clipped to +-5 -> exact).
__global__ void __launch_bounds__(256) edge_kernel(const int* __restrict__ ei,
                                                   const float* __restrict__ Aw)
{
    int e = (int)((blockIdx.x * (size_t)blockDim.x + threadIdx.x) >> 5);
    int l = threadIdx.x & 31;
    if (e >= EE) return;
    int dst = ei[e];
    int src = ei[EE + e];
    int c0 = l * 4;
    int h = l >> 2;
    int dbase = (l & 3) * 4;

    float4 q = *(const float4*)&g_Qh[(size_t)dst * HIDD + c0];
    float4 kk = *(const float4*)&g_Kh[(size_t)src * HIDD + c0];
    float4 ew = *(const float4*)&g_Eh[(size_t)e * 256 + c0];
    float4 eb = *(const float4*)&g_Eh[(size_t)e * 256 + 128 + c0];
    float4 vv = *(const float4*)&g_Vh[(size_t)src * HIDD + c0];

    const float* qf = (const float*)&q;
    const float* kf = (const float*)&kk;
    const float* ewf = (const float*)&ew;
    const float* ebf = (const float*)&eb;
    const float* vf = (const float*)&vv;

    float ce[4];
    float part = 0.f;
#pragma unroll
    for (int i = 0; i < 4; i++) {
        float m = qf[i] + kf[i];
        float cc = m * ewf[i];
        float ss = sqrtf(fabsf(cc));
        ss = (cc >= 0.f) ? ss : -ss;          // signed sqrt
        float val = ss + ebf[i];
        ce[i] = fmaxf(val, 0.f);
        part += ce[i] * Aw[(dbase + i) * NH + h];
    }
    *(float4*)&g_ce[(size_t)e * HIDD + c0] = make_float4(ce[0], ce[1], ce[2], ce[3]);

    part += __shfl_xor_sync(0xffffffffu, part, 1);
    part += __shfl_xor_sync(0xffffffffu, part, 2);
    float s = fminf(fmaxf(part, -5.f), 5.f);
    float p = __expf(s);

    if ((l & 3) == 0) atomicAdd(&g_ssum[(size_t)dst * NH + h], p);
    float4 av = make_float4(vf[0] * p, vf[1] * p, vf[2] * p, vf[3] * p);
    float4 rv = make_float4(ce[0] * p, ce[1] * p, ce[2] * p, ce[3] * p);
    atomicAdd((float4*)&g_agg[(size_t)dst * HIDD + c0], av);
    atomicAdd((float4*)&g_row[(size_t)dst * HIDD + c0], rv);
}

// ---------------- node pass: normalize, rowV = row @ Bw, deg scaling ----------------
__global__ void __launch_bounds__(256) node_kernel(const float* __restrict__ Bw,
                                                   const float* __restrict__ deg_coef,
                                                   const float* __restrict__ log_deg)
{
    __shared__ float rbuf[8][HIDD];
    int n = (int)((blockIdx.x * (size_t)blockDim.x + threadIdx.x) >> 5);
    int wl = (threadIdx.x >> 5) & 7;
    int l = threadIdx.x & 31;
    if (n >= NN) return;
    int h = l >> 2;
    int c0 = l * 4;

    float rs = 1.f / (g_ssum[(size_t)n * NH + h] + 1e-16f);
    float4 a = *(const float4*)&g_agg[(size_t)n * HIDD + c0];
    float4 r = *(const float4*)&g_row[(size_t)n * HIDD + c0];
    a.x *= rs; a.y *= rs; a.z *= rs; a.w *= rs;
    r.x *= rs; r.y *= rs; r.z *= rs; r.w *= rs;
    *(float4*)&rbuf[wl][c0] = r;
    __syncwarp();

    float4 q = *(const float4*)&g_Qh[(size_t)n * HIDD + c0];
    const float* af = (const float*)&a;
    const float* qf = (const float*)&q;
    float ld = log_deg[n];

    float out[4];
#pragma unroll
    for (int i = 0; i < 4; i++) {
        int c = c0 + i;
        float rv = 0.f;
#pragma unroll
        for (int d = 0; d < DDIM; d++)
            rv = fmaf(rbuf[wl][h * DDIM + d], __ldg(&Bw[d * HIDD + c]), rv);
        float ha = qf[i] + af[i] + rv;
        out[i] = ha * (deg_coef[2 * c] + ld * deg_coef[2 * c + 1]);
    }
    *(float4*)&g_hpre[(size_t)n * HIDD + c0] = make_float4(out[0], out[1], out[2], out[3]);
}

// ---------------- launch ----------------
extern "C" void kernel_launch(void* const* d_in, const int* in_sizes, int n_in,
                              void* d_out, int out_size)
{
    const float* x        = (const float*)d_in[0];
    const float* conn     = (const float*)d_in[1];
    const float* log_deg  = (const float*)d_in[2];
    const int*   ei       = (const int*)d_in[3];
    const float* WQ       = (const float*)d_in[4];
    const float* WK       = (const float*)d_in[5];
    const float* WV       = (const float*)d_in[6];
    const float* WE       = (const float*)d_in[7];
    const float* Aw       = (const float*)d_in[8];
    const float* Bw       = (const float*)d_in[9];
    const float* Ho_w     = (const float*)d_in[10];
    const float* Ho_b     = (const float*)d_in[11];
    const float* Eo_w     = (const float*)d_in[12];
    const float* Eo_b     = (const float*)d_in[13];
    const float* deg_coef = (const float*)d_in[14];
    const float* ln1h_g   = (const float*)d_in[15];
    const float* ln1h_b   = (const float*)d_in[16];
    const float* ln1e_g   = (const float*)d_in[17];
    const float* ln1e_b   = (const float*)d_in[18];
    const float* ln2h_g   = (const float*)d_in[19];
    const float* ln2h_b   = (const float*)d_in[20];
    const float* W1       = (const float*)d_in[21];
    const float* b1       = (const float*)d_in[22];
    const float* W2       = (const float*)d_in[23];
    const float* b2       = (const float*)d_in[24];

    float* out_h = (float*)d_out;
    float* out_e = out_h + (size_t)NN * HIDD;

    float *Qh, *Kh, *Vh, *Eh, *ce, *ssum, *agg, *row, *hpre, *h1, *mlp;
    cudaGetSymbolAddress((void**)&Qh, g_Qh);
    cudaGetSymbolAddress((void**)&Kh, g_Kh);
    cudaGetSymbolAddress((void**)&Vh, g_Vh);
    cudaGetSymbolAddress((void**)&Eh, g_Eh);
    cudaGetSymbolAddress((void**)&ce, g_ce);
    cudaGetSymbolAddress((void**)&ssum, g_ssum);
    cudaGetSymbolAddress((void**)&agg, g_agg);
    cudaGetSymbolAddress((void**)&row, g_row);
    cudaGetSymbolAddress((void**)&hpre, g_hpre);
    cudaGetSymbolAddress((void**)&h1, g_h1);
    cudaGetSymbolAddress((void**)&mlp, g_mlp);

    const int gN = (NN + 127) / 128;   // 391
    const int gE = (EE + 127) / 128;   // 4688

    cudaMemsetAsync(ssum, 0, (size_t)NN * NH * sizeof(float), 0);
    cudaMemsetAsync(agg, 0, (size_t)NN * HIDD * sizeof(float), 0);
    cudaMemsetAsync(row, 0, (size_t)NN * HIDD * sizeof(float), 0);

    // Qh, Kh, Vh
    tgemm<128, 0><<<dim3(gN, 1), 256>>>(x, WQ, 128, nullptr, nullptr, nullptr, nullptr, Qh, 128, NN);
    tgemm<128, 0><<<dim3(gN, 1), 256>>>(x, WK, 128, nullptr, nullptr, nullptr, nullptr, Kh, 128, NN);
    tgemm<128, 0><<<dim3(gN, 1), 256>>>(x, WV, 128, nullptr, nullptr, nullptr, nullptr, Vh, 128, NN);
    // Eh = conn @ WE  [E,256]
    tgemm<128, 0><<<dim3(gE, 2), 256>>>(conn, WE, 256, nullptr, nullptr, nullptr, nullptr, Eh, 256, EE);

    // edge pass (conn_e + softmax-weighted segment sums)
    edge_kernel<<<(EE * 32 + 255) / 256, 256>>>(ei, Aw);
    // node pass -> h_pre
    node_kernel<<<(NN * 32 + 255) / 256, 256>>>(Bw, deg_coef, log_deg);

    // h1 = LN1h(x + hpre @ Ho_w + Ho_b)
    tgemm<128, 2><<<dim3(gN, 1), 256>>>(hpre, Ho_w, 128, Ho_b, x, ln1h_g, ln1h_b, h1, 128, NN);
    // mlp = relu(h1 @ W1 + b1)
    tgemm<128, 1><<<dim3(gN, 2), 256>>>(h1, W1, 256, b1, nullptr, nullptr, nullptr, mlp, 256, NN);
    // out_h = LN2h(h1 + mlp @ W2 + b2)
    tgemm<256, 2><<<dim3(gN, 1), 256>>>(mlp, W2, 128, b2, h1, ln2h_g, ln2h_b, out_h, 128, NN);
    // out_e = LN1e(conn + ce @ Eo_w + Eo_b)
    tgemm<128, 2><<<dim3(gE, 1), 256>>>(ce, Eo_w, 128, Eo_b, conn, ln1e_g, ln1e_b, out_e, 128, EE);
}